// round 1
// baseline (speedup 1.0000x reference)
#include <cuda_runtime.h>
#include <cuda_bf16.h>
#include <mma.h>
#include <math.h>

using namespace nvcuda;

// Problem constants
#define SEQ    2048
#define EMB    512
#define HID    2048
#define NBATCH 2
#define MTOT   4096   // NBATCH*SEQ
#define NHEAD  8
#define DH     64

// Scratch (allocation-guard safe: __device__ globals)
__device__ float g_H[(size_t)MTOT * HID];   // 32 MB hidden activations
__device__ float g_Q[(size_t)MTOT * EMB];   // 8 MB q buffer

__device__ __forceinline__ float gelu_f(float x) {
    const float c = 0.7978845608028654f;  // sqrt(2/pi)
    float x3 = x * x * x;
    float t = tanhf(c * (x + 0.044715f * x3));
    return 0.5f * x * (1.0f + t);
}

__device__ __forceinline__ void store_tf32_4(float* p, float4 v) {
    p[0] = wmma::__float_to_tf32(v.x);
    p[1] = wmma::__float_to_tf32(v.y);
    p[2] = wmma::__float_to_tf32(v.z);
    p[3] = wmma::__float_to_tf32(v.w);
}

// ---------------------------------------------------------------------------
// Generic GEMM: C[M,N] = act(A[M,K] @ B[K,N] + bias[N]), tf32 wmma, fp32 acc.
// Tile 128x64, BK=16, 256 threads (8 warps, each 32x32 = 2x2 m16n16k8 frags).
// M%128==0, N%64==0, K%16==0 hold for all 6 uses.
// ---------------------------------------------------------------------------
template<int ACT>
__global__ void __launch_bounds__(256) gemm_bias_act(
    const float* __restrict__ A, const float* __restrict__ B,
    const float* __restrict__ bias, float* __restrict__ C,
    int M, int N, int K)
{
    __shared__ float sm[8192];           // 32 KB; reused for epilogue tile
    float* Asw[2] = { sm,        sm + 2048 };   // [128][16] each
    float* Bsw[2] = { sm + 4096, sm + 5120 };   // [16][64]  each

    const int t  = threadIdx.x;
    const int w  = t >> 5;
    const int wm = w >> 1;               // 0..3
    const int wn = w & 1;                // 0..1
    const int m0 = blockIdx.y * 128;
    const int n0 = blockIdx.x * 64;

    // A-tile loads: 128x16 floats = 512 float4, 2 per thread
    const int arow0 = t >> 2;
    const int arow1 = (t + 256) >> 2;
    const int ac4   = (t & 3) * 4;
    // B-tile loads: 16x64 floats = 256 float4, 1 per thread
    const int brow  = t >> 4;
    const int bc4   = (t & 15) * 4;

    const float* Aptr0 = A + (size_t)(m0 + arow0) * K + ac4;
    const float* Aptr1 = A + (size_t)(m0 + arow1) * K + ac4;
    const float* Bptr  = B + (size_t)brow * N + n0 + bc4;

    const int asoff0 = arow0 * 16 + ac4;
    const int asoff1 = arow1 * 16 + ac4;
    const int bsoff  = brow * 64 + bc4;

    wmma::fragment<wmma::accumulator, 16, 16, 8, float> acc[2][2];
    #pragma unroll
    for (int i = 0; i < 2; i++)
        #pragma unroll
        for (int j = 0; j < 2; j++)
            wmma::fill_fragment(acc[i][j], 0.0f);

    const int ntiles = K >> 4;

    // Prologue: tile 0 -> buffer 0
    float4 ra0 = *(const float4*)(Aptr0);
    float4 ra1 = *(const float4*)(Aptr1);
    float4 rb  = *(const float4*)(Bptr);
    store_tf32_4(Asw[0] + asoff0, ra0);
    store_tf32_4(Asw[0] + asoff1, ra1);
    store_tf32_4(Bsw[0] + bsoff,  rb);
    __syncthreads();

    for (int kt = 0; kt < ntiles; kt++) {
        const int buf = kt & 1;
        if (kt + 1 < ntiles) {
            ra0 = *(const float4*)(Aptr0 + (kt + 1) * 16);
            ra1 = *(const float4*)(Aptr1 + (kt + 1) * 16);
            rb  = *(const float4*)(Bptr + (size_t)(kt + 1) * 16 * N);
        }
        #pragma unroll
        for (int kk = 0; kk < 2; kk++) {
            wmma::fragment<wmma::matrix_a, 16, 16, 8, wmma::precision::tf32, wmma::row_major> af[2];
            wmma::fragment<wmma::matrix_b, 16, 16, 8, wmma::precision::tf32, wmma::row_major> bf[2];
            #pragma unroll
            for (int i = 0; i < 2; i++)
                wmma::load_matrix_sync(af[i], Asw[buf] + (wm * 32 + i * 16) * 16 + kk * 8, 16);
            #pragma unroll
            for (int j = 0; j < 2; j++)
                wmma::load_matrix_sync(bf[j], Bsw[buf] + (kk * 8) * 64 + wn * 32 + j * 16, 64);
            #pragma unroll
            for (int i = 0; i < 2; i++)
                #pragma unroll
                for (int j = 0; j < 2; j++)
                    wmma::mma_sync(acc[i][j], af[i], bf[j], acc[i][j]);
        }
        if (kt + 1 < ntiles) {
            store_tf32_4(Asw[buf ^ 1] + asoff0, ra0);
            store_tf32_4(Asw[buf ^ 1] + asoff1, ra1);
            store_tf32_4(Bsw[buf ^ 1] + bsoff,  rb);
        }
        __syncthreads();
    }

    // Epilogue: stash accumulators in smem (reuse), then bias (+gelu) + store
    float* Cs = sm;   // [128][64]
    #pragma unroll
    for (int i = 0; i < 2; i++)
        #pragma unroll
        for (int j = 0; j < 2; j++)
            wmma::store_matrix_sync(Cs + (wm * 32 + i * 16) * 64 + wn * 32 + j * 16,
                                    acc[i][j], 64, wmma::mem_row_major);
    __syncthreads();

    for (int v = t; v < 2048; v += 256) {
        int row = v >> 4;
        int c4  = (v & 15) * 4;
        float4 val = *(float4*)(Cs + row * 64 + c4);
        int gc = n0 + c4;
        val.x += bias[gc + 0];
        val.y += bias[gc + 1];
        val.z += bias[gc + 2];
        val.w += bias[gc + 3];
        if (ACT) {
            val.x = gelu_f(val.x);
            val.y = gelu_f(val.y);
            val.z = gelu_f(val.z);
            val.w = gelu_f(val.w);
        }
        *(float4*)(C + (size_t)(m0 + row) * N + gc) = val;
    }
}

// ---------------------------------------------------------------------------
// Flash attention (causal), Dh=64. One CTA = one (batch-head, 64 q rows).
// tf32 wmma for QK^T and PV; online softmax; O accumulator in smem so per-row
// rescale stays independent of the opaque wmma fragment layout.
// smem (floats): Q[64][72], K[64][72], V[64][72], S[64][72], O[64][72], m[64], l[64]
// ---------------------------------------------------------------------------
#define LDP 72
#define FLASH_SMEM_FLOATS (5 * 64 * LDP + 128)
#define FLASH_SMEM_BYTES  (FLASH_SMEM_FLOATS * 4)

__global__ void __launch_bounds__(128) flash_attn(
    const float* __restrict__ Q, const float* __restrict__ K,
    const float* __restrict__ V, float* __restrict__ O)
{
    extern __shared__ float sm[];
    float* Qt = sm;
    float* Kt = sm + 1 * 64 * LDP;
    float* Vt = sm + 2 * 64 * LDP;
    float* Sb = sm + 3 * 64 * LDP;
    float* Ob = sm + 4 * 64 * LDP;
    float* mrow = sm + 5 * 64 * LDP;
    float* lrow = mrow + 64;

    const int t = threadIdx.x;
    const int w = t >> 5;                 // warp 0..3, rows [16w, 16w+16)
    const int qblk = blockIdx.x;          // 0..31
    const int bh   = blockIdx.y;          // 0..15
    const int b = bh >> 3;
    const int h = bh & 7;

    const size_t hbase = (size_t)b * SEQ * EMB + (size_t)h * DH;
    const float* Qg = Q + hbase + (size_t)qblk * 64 * EMB;
    const float* Kg = K + hbase;
    const float* Vg = V + hbase;
    float*       Og = O + hbase + (size_t)qblk * 64 * EMB;

    // Load Q tile (->tf32), zero O
    for (int v = t; v < 1024; v += 128) {
        int row = v >> 4, c = (v & 15) * 4;
        float4 q4 = *(const float4*)(Qg + (size_t)row * EMB + c);
        store_tf32_4(Qt + row * LDP + c, q4);
        float* o = Ob + row * LDP + c;
        o[0] = 0.f; o[1] = 0.f; o[2] = 0.f; o[3] = 0.f;
    }
    if (t < 64) { mrow[t] = -INFINITY; lrow[t] = 0.f; }
    __syncthreads();

    const float scale = 0.125f;   // 1/sqrt(64)

    for (int j = 0; j <= qblk; j++) {
        // Load K/V tiles (->tf32)
        for (int v = t; v < 1024; v += 128) {
            int row = v >> 4, c = (v & 15) * 4;
            float4 k4 = *(const float4*)(Kg + (size_t)(j * 64 + row) * EMB + c);
            float4 v4 = *(const float4*)(Vg + (size_t)(j * 64 + row) * EMB + c);
            store_tf32_4(Kt + row * LDP + c, k4);
            store_tf32_4(Vt + row * LDP + c, v4);
        }
        __syncthreads();

        // S = Q @ K^T  (warp w: rows [16w,16w+16) x all 64 cols)
        {
            wmma::fragment<wmma::accumulator, 16, 16, 8, float> sacc[4];
            #pragma unroll
            for (int nf = 0; nf < 4; nf++) wmma::fill_fragment(sacc[nf], 0.0f);
            #pragma unroll
            for (int kk = 0; kk < 8; kk++) {
                wmma::fragment<wmma::matrix_a, 16, 16, 8, wmma::precision::tf32, wmma::row_major> af;
                wmma::load_matrix_sync(af, Qt + (w * 16) * LDP + kk * 8, LDP);
                #pragma unroll
                for (int nf = 0; nf < 4; nf++) {
                    wmma::fragment<wmma::matrix_b, 16, 16, 8, wmma::precision::tf32, wmma::col_major> bf;
                    wmma::load_matrix_sync(bf, Kt + (nf * 16) * LDP + kk * 8, LDP);
                    wmma::mma_sync(sacc[nf], af, bf, sacc[nf]);
                }
            }
            #pragma unroll
            for (int nf = 0; nf < 4; nf++)
                wmma::store_matrix_sync(Sb + (w * 16) * LDP + nf * 16, sacc[nf], LDP, wmma::mem_row_major);
        }
        __syncthreads();

        // Online softmax: 2 threads per row (32 cols each)
        {
            int r = t >> 1;
            int half = t & 1;
            int cbase = half * 32;
            int qg = qblk * 64 + r;
            float sv[32];
            float pm = -INFINITY;
            #pragma unroll
            for (int i = 0; i < 32; i++) {
                int c = cbase + i;
                float s = Sb[r * LDP + c] * scale;
                if (j * 64 + c > qg) s = -INFINITY;   // causal (DIAGONAL=1)
                sv[i] = s;
                pm = fmaxf(pm, s);
            }
            float rmax = fmaxf(pm, __shfl_xor_sync(0xffffffffu, pm, 1));
            float mo = mrow[r];
            float mn = fmaxf(mo, rmax);
            float corr = __expf(mo - mn);             // 0 on first block (mo=-inf)
            float ps = 0.f;
            #pragma unroll
            for (int i = 0; i < 32; i++) {
                float p = __expf(sv[i] - mn);
                ps += p;
                Sb[r * LDP + cbase + i] = wmma::__float_to_tf32(p);
            }
            float tot = ps + __shfl_xor_sync(0xffffffffu, ps, 1);
            #pragma unroll
            for (int i = 0; i < 32; i++) Ob[r * LDP + cbase + i] *= corr;
            if (half == 0) { mrow[r] = mn; lrow[r] = lrow[r] * corr + tot; }
        }
        __syncthreads();

        // O += P @ V
        {
            wmma::fragment<wmma::accumulator, 16, 16, 8, float> oacc[4];
            #pragma unroll
            for (int nf = 0; nf < 4; nf++)
                wmma::load_matrix_sync(oacc[nf], Ob + (w * 16) * LDP + nf * 16, LDP, wmma::mem_row_major);
            #pragma unroll
            for (int kk = 0; kk < 8; kk++) {
                wmma::fragment<wmma::matrix_a, 16, 16, 8, wmma::precision::tf32, wmma::row_major> af;
                wmma::load_matrix_sync(af, Sb + (w * 16) * LDP + kk * 8, LDP);
                #pragma unroll
                for (int nf = 0; nf < 4; nf++) {
                    wmma::fragment<wmma::matrix_b, 16, 16, 8, wmma::precision::tf32, wmma::row_major> bf;
                    wmma::load_matrix_sync(bf, Vt + (kk * 8) * LDP + nf * 16, LDP);
                    wmma::mma_sync(oacc[nf], af, bf, oacc[nf]);
                }
            }
            #pragma unroll
            for (int nf = 0; nf < 4; nf++)
                wmma::store_matrix_sync(Ob + (w * 16) * LDP + nf * 16, oacc[nf], LDP, wmma::mem_row_major);
        }
        __syncthreads();
    }

    // Finalize: O / l -> global
    for (int v = t; v < 1024; v += 128) {
        int row = v >> 4, c = (v & 15) * 4;
        float inv = 1.0f / lrow[row];
        float4 o4 = *(float4*)(Ob + row * LDP + c);
        o4.x *= inv; o4.y *= inv; o4.z *= inv; o4.w *= inv;
        *(float4*)(Og + (size_t)row * EMB + c) = o4;
    }
}

// ---------------------------------------------------------------------------
// Host launcher. Output layout: concat(k, v, out), each [2,2048,512] fp32.
// ---------------------------------------------------------------------------
extern "C" void kernel_launch(void* const* d_in, const int* in_sizes, int n_in,
                              void* d_out, int out_size)
{
    const float* x   = (const float*)d_in[0];
    const float* qW1 = (const float*)d_in[1];
    const float* qb1 = (const float*)d_in[2];
    const float* qW2 = (const float*)d_in[3];
    const float* qb2 = (const float*)d_in[4];
    const float* kW1 = (const float*)d_in[5];
    const float* kb1 = (const float*)d_in[6];
    const float* kW2 = (const float*)d_in[7];
    const float* kb2 = (const float*)d_in[8];
    const float* vW1 = (const float*)d_in[9];
    const float* vb1 = (const float*)d_in[10];
    const float* vW2 = (const float*)d_in[11];
    const float* vb2 = (const float*)d_in[12];

    float* outp = (float*)d_out;
    float* kOut = outp;
    float* vOut = outp + (size_t)MTOT * EMB;
    float* oOut = outp + (size_t)2 * MTOT * EMB;

    float* H = nullptr;
    float* Qbuf = nullptr;
    cudaGetSymbolAddress((void**)&H, g_H);
    cudaGetSymbolAddress((void**)&Qbuf, g_Q);

    dim3 gridH(HID / 64, MTOT / 128);   // x@W1 : [4096,512]x[512,2048]
    dim3 gridE(EMB / 64, MTOT / 128);   // h@W2 : [4096,2048]x[2048,512]

    // K path
    gemm_bias_act<1><<<gridH, 256>>>(x, kW1, kb1, H, MTOT, HID, EMB);
    gemm_bias_act<0><<<gridE, 256>>>(H, kW2, kb2, kOut, MTOT, EMB, HID);
    // V path (extra trailing GELU)
    gemm_bias_act<1><<<gridH, 256>>>(x, vW1, vb1, H, MTOT, HID, EMB);
    gemm_bias_act<1><<<gridE, 256>>>(H, vW2, vb2, vOut, MTOT, EMB, HID);
    // Q path
    gemm_bias_act<1><<<gridH, 256>>>(x, qW1, qb1, H, MTOT, HID, EMB);
    gemm_bias_act<0><<<gridE, 256>>>(H, qW2, qb2, Qbuf, MTOT, EMB, HID);

    // Attention
    cudaFuncSetAttribute(flash_attn, cudaFuncAttributeMaxDynamicSharedMemorySize,
                         FLASH_SMEM_BYTES);
    flash_attn<<<dim3(SEQ / 64, NBATCH * NHEAD), 128, FLASH_SMEM_BYTES>>>(
        Qbuf, kOut, vOut, oOut);
}

// round 5
// speedup vs baseline: 3.9822x; 3.9822x over previous
#include <cuda_runtime.h>
#include <cuda_fp16.h>
#include <mma.h>
#include <math.h>
#include <stdint.h>

using namespace nvcuda;

// Problem constants
#define SEQ    2048
#define EMB    512
#define HID    2048
#define NBATCH 2
#define MTOT   4096   // NBATCH*SEQ
#define NHEAD  8
#define DH     64

// ---------------------------------------------------------------------------
// Device scratch (allocation-guard safe)
// ---------------------------------------------------------------------------
__device__ __half g_Hh[(size_t)MTOT * HID];     // 16 MB hidden activations (fp16)
__device__ __half g_Qh[(size_t)MTOT * EMB];     // 4 MB q buffer (fp16)
__device__ __half g_xh[(size_t)MTOT * EMB];     // 4 MB x in fp16
__device__ __half g_Wt[(size_t)6 * EMB * HID];  // 12 MB transposed fp16 weights

__device__ __forceinline__ float gelu_f(float x) {
    const float c = 0.7978845608028654f;  // sqrt(2/pi)
    float x3 = x * x * x;
    float t = tanhf(c * (x + 0.044715f * x3));
    return 0.5f * x * (1.0f + t);
}

__device__ __forceinline__ uint32_t smem_u32(const void* p) {
    uint32_t a;
    asm("{ .reg .u64 t; cvta.to.shared.u64 t, %1; cvt.u32.u64 %0, t; }" : "=r"(a) : "l"(p));
    return a;
}

__device__ __forceinline__ void cp_async16(uint32_t sdst, const void* gsrc) {
    asm volatile("cp.async.cg.shared.global [%0], [%1], 16;" :: "r"(sdst), "l"(gsrc));
}
#define CP_COMMIT() asm volatile("cp.async.commit_group;" ::: "memory")
#define CP_WAIT1()  asm volatile("cp.async.wait_group 1;" ::: "memory")

#define LDSM4(r, addr) \
    asm volatile("ldmatrix.sync.aligned.m8n8.x4.shared.b16 {%0,%1,%2,%3}, [%4];" \
        : "=r"((r)[0]), "=r"((r)[1]), "=r"((r)[2]), "=r"((r)[3]) : "r"(addr))

#define MMA16816(c, a, b0, b1) \
    asm volatile("mma.sync.aligned.m16n8k16.row.col.f32.f16.f16.f32 " \
        "{%0,%1,%2,%3}, {%4,%5,%6,%7}, {%8,%9}, {%0,%1,%2,%3};" \
        : "+f"((c)[0]), "+f"((c)[1]), "+f"((c)[2]), "+f"((c)[3]) \
        : "r"((a)[0]), "r"((a)[1]), "r"((a)[2]), "r"((a)[3]), "r"(b0), "r"(b1))

// ---------------------------------------------------------------------------
// FP16 GEMM: C[M,N] = act(A[M,K] @ Bt[N,K]^T + bias)
//   CTA 128x128, BK=64 halves (128B rows), 8 warps (2x4), warp tile 64x32.
//   3-stage cp.async pipeline, XOR-swizzled smem, ldmatrix + mma.m16n8k16.
// ---------------------------------------------------------------------------
#define STAGE_B 32768   // 16KB A + 16KB B
#define NST     3
#define GSMEM   (NST * STAGE_B)

template<int ACT, int OUTH>
__global__ void __launch_bounds__(256, 2)
gemm_f16(const __half* __restrict__ A, const __half* __restrict__ Bt,
         const float* __restrict__ bias, void* __restrict__ Cout,
         int M, int N, int K)
{
    extern __shared__ char smem[];
    const uint32_t sb = smem_u32(smem);
    const int tid  = threadIdx.x;
    const int lane = tid & 31;
    const int wid  = tid >> 5;
    const int wm   = wid >> 2;            // 0..1 (64-row slabs)
    const int wn   = wid & 3;             // 0..3 (32-col slabs)
    const int m0 = blockIdx.y * 128;
    const int n0 = blockIdx.x * 128;
    const int KT = K >> 6;                // k-tiles of 64 halves

    // stage-load geometry: 1024 16B chunks per operand, 4 per thread
    int lrowv[4]; uint32_t lsoffv[4]; int luv[4];
    #pragma unroll
    for (int i = 0; i < 4; i++) {
        int idx = i * 256 + tid;
        int row = idx >> 3, u = idx & 7;
        lrowv[i] = row; luv[i] = u;
        lsoffv[i] = (uint32_t)(row * 128 + ((u ^ (row & 7)) * 16));
    }

    auto load_stage = [&](int kt, int s) {
        const uint32_t sA = sb + s * STAGE_B;
        const uint32_t sB = sA + 16384;
        const int k0 = kt * 64;
        #pragma unroll
        for (int i = 0; i < 4; i++) {
            cp_async16(sA + lsoffv[i], A  + (size_t)(m0 + lrowv[i]) * K + k0 + luv[i] * 8);
            cp_async16(sB + lsoffv[i], Bt + (size_t)(n0 + lrowv[i]) * K + k0 + luv[i] * 8);
        }
    };

    // ldmatrix per-thread geometry
    const int seg  = lane >> 3;
    const int lrow = lane & 7;
    const int arow = wm * 64 + lrow + (seg & 1) * 8;   // + am*16
    const int auseg = seg >> 1;                        // k-unit offset
    const int ax7  = arow & 7;
    const int brow = wn * 32 + lrow + (seg >> 1) * 8;  // + bp*16
    const int buseg = seg & 1;
    const int bx7  = brow & 7;

    float acc[4][4][4];
    #pragma unroll
    for (int i = 0; i < 4; i++)
        #pragma unroll
        for (int j = 0; j < 4; j++)
            #pragma unroll
            for (int r = 0; r < 4; r++) acc[i][j][r] = 0.0f;

    load_stage(0, 0); CP_COMMIT();
    load_stage(1, 1); CP_COMMIT();

    for (int kt = 0; kt < KT; kt++) {
        CP_WAIT1();
        __syncthreads();
        if (kt + 2 < KT) load_stage(kt + 2, (kt + 2) % 3);
        CP_COMMIT();

        const uint32_t sA = sb + (kt % 3) * STAGE_B;
        const uint32_t sB = sA + 16384;
        #pragma unroll
        for (int kk = 0; kk < 4; kk++) {
            uint32_t af[4][4];
            #pragma unroll
            for (int am = 0; am < 4; am++) {
                uint32_t row = arow + am * 16;
                uint32_t unit = (uint32_t)((2 * kk + auseg) ^ ax7);
                LDSM4(af[am], sA + row * 128 + unit * 16);
            }
            uint32_t bf[2][4];
            #pragma unroll
            for (int bp = 0; bp < 2; bp++) {
                uint32_t row = brow + bp * 16;
                uint32_t unit = (uint32_t)((2 * kk + buseg) ^ bx7);
                LDSM4(bf[bp], sB + row * 128 + unit * 16);
            }
            #pragma unroll
            for (int am = 0; am < 4; am++)
                #pragma unroll
                for (int bn = 0; bn < 4; bn++)
                    MMA16816(acc[am][bn], af[am],
                             bf[bn >> 1][(bn & 1) * 2], bf[bn >> 1][(bn & 1) * 2 + 1]);
        }
    }

    // epilogue: bias + act + store (f32 or f16)
    const int g   = lane >> 2;
    const int tig = lane & 3;
    #pragma unroll
    for (int am = 0; am < 4; am++) {
        #pragma unroll
        for (int bn = 0; bn < 4; bn++) {
            int grow = m0 + wm * 64 + am * 16 + g;
            int gcol = n0 + wn * 32 + bn * 8 + 2 * tig;
            float2 bb = *(const float2*)(bias + gcol);
            float v0 = acc[am][bn][0] + bb.x;
            float v1 = acc[am][bn][1] + bb.y;
            float v2 = acc[am][bn][2] + bb.x;
            float v3 = acc[am][bn][3] + bb.y;
            if (ACT) { v0 = gelu_f(v0); v1 = gelu_f(v1); v2 = gelu_f(v2); v3 = gelu_f(v3); }
            if (OUTH) {
                __half* Ch = (__half*)Cout;
                *(__half2*)(Ch + (size_t)grow * N + gcol)       = __floats2half2_rn(v0, v1);
                *(__half2*)(Ch + (size_t)(grow + 8) * N + gcol) = __floats2half2_rn(v2, v3);
            } else {
                float* Cf = (float*)Cout;
                *(float2*)(Cf + (size_t)grow * N + gcol)       = make_float2(v0, v1);
                *(float2*)(Cf + (size_t)(grow + 8) * N + gcol) = make_float2(v2, v3);
            }
        }
    }
}

// ---------------------------------------------------------------------------
// Pre-pass: x -> fp16 ; transpose weights [K][N] f32 -> [N][K] fp16
// ---------------------------------------------------------------------------
__global__ void f2h_kernel(const float* __restrict__ in, __half* __restrict__ out, int n4) {
    int i = blockIdx.x * blockDim.x + threadIdx.x;
    if (i < n4) {
        float4 v = ((const float4*)in)[i];
        ((__half2*)out)[2 * i]     = __floats2half2_rn(v.x, v.y);
        ((__half2*)out)[2 * i + 1] = __floats2half2_rn(v.z, v.w);
    }
}

__global__ void transpose_f2h(const float* __restrict__ in, __half* __restrict__ out,
                              int R, int C) {   // in [R][C] -> out [C][R]
    __shared__ float t[32][33];
    int bx = blockIdx.x * 32;   // over C
    int by = blockIdx.y * 32;   // over R
    int tx = threadIdx.x, ty = threadIdx.y;
    #pragma unroll
    for (int i = 0; i < 32; i += 8)
        t[ty + i][tx] = in[(size_t)(by + ty + i) * C + bx + tx];
    __syncthreads();
    #pragma unroll
    for (int i = 0; i < 32; i += 8)
        out[(size_t)(bx + ty + i) * R + by + tx] = __float2half_rn(t[tx][ty + i]);
}

// ---------------------------------------------------------------------------
// Flash attention (causal), Dh=64, fp16 wmma m16n16k16.
// One CTA = (batch-head, 64 q rows), 128 threads (4 warps).
// ---------------------------------------------------------------------------
#define ALDP 80   // padded leading dim (halves / floats)
#define ATT_SMEM (4 * 64 * ALDP * 2 + 2 * 64 * ALDP * 4 + 512)

__global__ void __launch_bounds__(128) flash_attn(
    const __half* __restrict__ Q, const float* __restrict__ K,
    const float* __restrict__ V, float* __restrict__ O)
{
    extern __shared__ char sma[];
    __half* Qt = (__half*)sma;
    __half* Kt = Qt + 64 * ALDP;
    __half* Vt = Kt + 64 * ALDP;
    __half* Pb = Vt + 64 * ALDP;
    float* Sb  = (float*)(Pb + 64 * ALDP);
    float* Ob  = Sb + 64 * ALDP;
    float* mrow = Ob + 64 * ALDP;
    float* lrow = mrow + 64;

    const int t = threadIdx.x;
    const int w = t >> 5;
    const int qblk = blockIdx.x;
    const int bh   = blockIdx.y;
    const int b = bh >> 3;
    const int h = bh & 7;

    const size_t hbase = (size_t)b * SEQ * EMB + (size_t)h * DH;
    const __half* Qg = Q + hbase + (size_t)qblk * 64 * EMB;
    const float*  Kg = K + hbase;
    const float*  Vg = V + hbase;
    float*        Og = O + hbase + (size_t)qblk * 64 * EMB;

    // Load Q (fp16, vectorized), zero O
    for (int v = t; v < 512; v += 128) {
        int row = v >> 3, c8 = (v & 7) * 8;
        *(uint4*)(Qt + row * ALDP + c8) = *(const uint4*)(Qg + (size_t)row * EMB + c8);
    }
    for (int v = t; v < 1024; v += 128) {
        int row = v >> 4, c = (v & 15) * 4;
        float* o = Ob + row * ALDP + c;
        o[0] = 0.f; o[1] = 0.f; o[2] = 0.f; o[3] = 0.f;
    }
    if (t < 64) { mrow[t] = -INFINITY; lrow[t] = 0.f; }
    __syncthreads();

    const float scale = 0.125f;   // 1/sqrt(64)

    for (int j = 0; j <= qblk; j++) {
        // Load K/V tiles (f32 -> f16)
        for (int v = t; v < 1024; v += 128) {
            int row = v >> 4, c = (v & 15) * 4;
            float4 k4 = *(const float4*)(Kg + (size_t)(j * 64 + row) * EMB + c);
            float4 v4 = *(const float4*)(Vg + (size_t)(j * 64 + row) * EMB + c);
            *(__half2*)(Kt + row * ALDP + c)     = __floats2half2_rn(k4.x, k4.y);
            *(__half2*)(Kt + row * ALDP + c + 2) = __floats2half2_rn(k4.z, k4.w);
            *(__half2*)(Vt + row * ALDP + c)     = __floats2half2_rn(v4.x, v4.y);
            *(__half2*)(Vt + row * ALDP + c + 2) = __floats2half2_rn(v4.z, v4.w);
        }
        __syncthreads();

        // S = Q @ K^T
        {
            wmma::fragment<wmma::accumulator, 16, 16, 16, float> sacc[4];
            #pragma unroll
            for (int nf = 0; nf < 4; nf++) wmma::fill_fragment(sacc[nf], 0.0f);
            #pragma unroll
            for (int kk = 0; kk < 4; kk++) {
                wmma::fragment<wmma::matrix_a, 16, 16, 16, __half, wmma::row_major> af;
                wmma::load_matrix_sync(af, Qt + (w * 16) * ALDP + kk * 16, ALDP);
                #pragma unroll
                for (int nf = 0; nf < 4; nf++) {
                    wmma::fragment<wmma::matrix_b, 16, 16, 16, __half, wmma::col_major> bf;
                    wmma::load_matrix_sync(bf, Kt + (nf * 16) * ALDP + kk * 16, ALDP);
                    wmma::mma_sync(sacc[nf], af, bf, sacc[nf]);
                }
            }
            #pragma unroll
            for (int nf = 0; nf < 4; nf++)
                wmma::store_matrix_sync(Sb + (w * 16) * ALDP + nf * 16, sacc[nf], ALDP, wmma::mem_row_major);
        }
        __syncthreads();

        // Online softmax: 2 threads per row
        {
            int r = t >> 1;
            int half_ = t & 1;
            int cbase = half_ * 32;
            int qg = qblk * 64 + r;
            float sv[32];
            float pm = -INFINITY;
            #pragma unroll
            for (int i = 0; i < 32; i++) {
                int c = cbase + i;
                float s = Sb[r * ALDP + c] * scale;
                if (j * 64 + c > qg) s = -INFINITY;   // causal
                sv[i] = s;
                pm = fmaxf(pm, s);
            }
            float rmax = fmaxf(pm, __shfl_xor_sync(0xffffffffu, pm, 1));
            float mo = mrow[r];
            float mn = fmaxf(mo, rmax);
            float corr = __expf(mo - mn);
            float ps = 0.f;
            #pragma unroll
            for (int i = 0; i < 32; i++) {
                float p = __expf(sv[i] - mn);
                ps += p;
                Pb[r * ALDP + cbase + i] = __float2half_rn(p);
            }
            float tot = ps + __shfl_xor_sync(0xffffffffu, ps, 1);
            #pragma unroll
            for (int i = 0; i < 32; i++) Ob[r * ALDP + cbase + i] *= corr;
            if (half_ == 0) { mrow[r] = mn; lrow[r] = lrow[r] * corr + tot; }
        }
        __syncthreads();

        // O += P @ V
        {
            wmma::fragment<wmma::accumulator, 16, 16, 16, float> oacc[4];
            #pragma unroll
            for (int nf = 0; nf < 4; nf++)
                wmma::load_matrix_sync(oacc[nf], Ob + (w * 16) * ALDP + nf * 16, ALDP, wmma::mem_row_major);
            #pragma unroll
            for (int kk = 0; kk < 4; kk++) {
                wmma::fragment<wmma::matrix_a, 16, 16, 16, __half, wmma::row_major> af;
                wmma::load_matrix_sync(af, Pb + (w * 16) * ALDP + kk * 16, ALDP);
                #pragma unroll
                for (int nf = 0; nf < 4; nf++) {
                    wmma::fragment<wmma::matrix_b, 16, 16, 16, __half, wmma::row_major> bf;
                    wmma::load_matrix_sync(bf, Vt + (kk * 16) * ALDP + nf * 16, ALDP);
                    wmma::mma_sync(oacc[nf], af, bf, oacc[nf]);
                }
            }
            #pragma unroll
            for (int nf = 0; nf < 4; nf++)
                wmma::store_matrix_sync(Ob + (w * 16) * ALDP + nf * 16, oacc[nf], ALDP, wmma::mem_row_major);
        }
        __syncthreads();
    }

    // Finalize
    for (int v = t; v < 1024; v += 128) {
        int row = v >> 4, c = (v & 15) * 4;
        float inv = 1.0f / lrow[row];
        float4 o4 = *(float4*)(Ob + row * ALDP + c);
        o4.x *= inv; o4.y *= inv; o4.z *= inv; o4.w *= inv;
        *(float4*)(Og + (size_t)row * EMB + c) = o4;
    }
}

// ---------------------------------------------------------------------------
// Host launcher. Output layout: concat(k, v, out), each [2,2048,512] fp32.
// ---------------------------------------------------------------------------
extern "C" void kernel_launch(void* const* d_in, const int* in_sizes, int n_in,
                              void* d_out, int out_size)
{
    const float* x   = (const float*)d_in[0];
    const float* qW1 = (const float*)d_in[1];
    const float* qb1 = (const float*)d_in[2];
    const float* qW2 = (const float*)d_in[3];
    const float* qb2 = (const float*)d_in[4];
    const float* kW1 = (const float*)d_in[5];
    const float* kb1 = (const float*)d_in[6];
    const float* kW2 = (const float*)d_in[7];
    const float* kb2 = (const float*)d_in[8];
    const float* vW1 = (const float*)d_in[9];
    const float* vb1 = (const float*)d_in[10];
    const float* vW2 = (const float*)d_in[11];
    const float* vb2 = (const float*)d_in[12];

    float* outp = (float*)d_out;
    float* kOut = outp;
    float* vOut = outp + (size_t)MTOT * EMB;
    float* oOut = outp + (size_t)2 * MTOT * EMB;

    __half *Hh = nullptr, *Qh = nullptr, *xh = nullptr, *Wt = nullptr;
    cudaGetSymbolAddress((void**)&Hh, g_Hh);
    cudaGetSymbolAddress((void**)&Qh, g_Qh);
    cudaGetSymbolAddress((void**)&xh, g_xh);
    cudaGetSymbolAddress((void**)&Wt, g_Wt);

    const size_t WSZ = (size_t)EMB * HID;
    __half* qW1t = Wt + 0 * WSZ;
    __half* qW2t = Wt + 1 * WSZ;
    __half* kW1t = Wt + 2 * WSZ;
    __half* kW2t = Wt + 3 * WSZ;
    __half* vW1t = Wt + 4 * WSZ;
    __half* vW2t = Wt + 5 * WSZ;

    // Pre-pass
    f2h_kernel<<<(MTOT * EMB / 4 + 255) / 256, 256>>>(x, xh, MTOT * EMB / 4);
    dim3 tpb(32, 8);
    dim3 tg1(HID / 32, EMB / 32);   // W1 [512][2048] -> [2048][512]
    dim3 tg2(EMB / 32, HID / 32);   // W2 [2048][512] -> [512][2048]
    transpose_f2h<<<tg1, tpb>>>(qW1, qW1t, EMB, HID);
    transpose_f2h<<<tg2, tpb>>>(qW2, qW2t, HID, EMB);
    transpose_f2h<<<tg1, tpb>>>(kW1, kW1t, EMB, HID);
    transpose_f2h<<<tg2, tpb>>>(kW2, kW2t, HID, EMB);
    transpose_f2h<<<tg1, tpb>>>(vW1, vW1t, EMB, HID);
    transpose_f2h<<<tg2, tpb>>>(vW2, vW2t, HID, EMB);

    cudaFuncSetAttribute(gemm_f16<1,1>, cudaFuncAttributeMaxDynamicSharedMemorySize, GSMEM);
    cudaFuncSetAttribute(gemm_f16<0,0>, cudaFuncAttributeMaxDynamicSharedMemorySize, GSMEM);
    cudaFuncSetAttribute(gemm_f16<1,0>, cudaFuncAttributeMaxDynamicSharedMemorySize, GSMEM);
    cudaFuncSetAttribute(gemm_f16<0,1>, cudaFuncAttributeMaxDynamicSharedMemorySize, GSMEM);

    dim3 grid1(HID / 128, MTOT / 128);   // 16 x 32
    dim3 grid2(EMB / 128, MTOT / 128);   // 4  x 32

    // K path
    gemm_f16<1,1><<<grid1, 256, GSMEM>>>(xh, kW1t, kb1, Hh, MTOT, HID, EMB);
    gemm_f16<0,0><<<grid2, 256, GSMEM>>>(Hh, kW2t, kb2, kOut, MTOT, EMB, HID);
    // V path (trailing GELU)
    gemm_f16<1,1><<<grid1, 256, GSMEM>>>(xh, vW1t, vb1, Hh, MTOT, HID, EMB);
    gemm_f16<1,0><<<grid2, 256, GSMEM>>>(Hh, vW2t, vb2, vOut, MTOT, EMB, HID);
    // Q path (output fp16 straight into attention input)
    gemm_f16<1,1><<<grid1, 256, GSMEM>>>(xh, qW1t, qb1, Hh, MTOT, HID, EMB);
    gemm_f16<0,1><<<grid2, 256, GSMEM>>>(Hh, qW2t, qb2, Qh, MTOT, EMB, HID);

    // Attention
    cudaFuncSetAttribute(flash_attn, cudaFuncAttributeMaxDynamicSharedMemorySize, ATT_SMEM);
    flash_attn<<<dim3(SEQ / 64, NBATCH * NHEAD), 128, ATT_SMEM>>>(Qh, kOut, vOut, oOut);
}

// round 6
// speedup vs baseline: 5.8188x; 1.4612x over previous
#include <cuda_runtime.h>
#include <cuda_fp16.h>
#include <math.h>
#include <stdint.h>

// Problem constants
#define SEQ    2048
#define EMB    512
#define HID    2048
#define NBATCH 2
#define MTOT   4096   // NBATCH*SEQ
#define NHEAD  8
#define DH     64

// ---------------------------------------------------------------------------
// Device scratch (allocation-guard safe)
// ---------------------------------------------------------------------------
__device__ __half g_Hh[(size_t)MTOT * HID];     // 16 MB hidden activations (fp16)
__device__ __half g_Qh[(size_t)MTOT * EMB];     // 4 MB q buffer (fp16)
__device__ __half g_Kh[(size_t)MTOT * EMB];     // 4 MB k fp16 copy
__device__ __half g_Vh[(size_t)MTOT * EMB];     // 4 MB v fp16 copy
__device__ __half g_xh[(size_t)MTOT * EMB];     // 4 MB x in fp16
__device__ __half g_Wt[(size_t)6 * EMB * HID];  // 12 MB transposed fp16 weights

__device__ __forceinline__ float gelu_f(float x) {
    const float c = 0.7978845608028654f;  // sqrt(2/pi)
    float x3 = x * x * x;
    float t = tanhf(c * (x + 0.044715f * x3));
    return 0.5f * x * (1.0f + t);
}

__device__ __forceinline__ uint32_t smem_u32(const void* p) {
    uint32_t a;
    asm("{ .reg .u64 t; cvta.to.shared.u64 t, %1; cvt.u32.u64 %0, t; }" : "=r"(a) : "l"(p));
    return a;
}

__device__ __forceinline__ void cp_async16(uint32_t sdst, const void* gsrc) {
    asm volatile("cp.async.cg.shared.global [%0], [%1], 16;" :: "r"(sdst), "l"(gsrc));
}
#define CP_COMMIT() asm volatile("cp.async.commit_group;" ::: "memory")
#define CP_WAIT1()  asm volatile("cp.async.wait_group 1;" ::: "memory")

#define LDSM4(r, addr) \
    asm volatile("ldmatrix.sync.aligned.m8n8.x4.shared.b16 {%0,%1,%2,%3}, [%4];" \
        : "=r"((r)[0]), "=r"((r)[1]), "=r"((r)[2]), "=r"((r)[3]) : "r"(addr))

#define LDSM4T(r, addr) \
    asm volatile("ldmatrix.sync.aligned.m8n8.x4.trans.shared.b16 {%0,%1,%2,%3}, [%4];" \
        : "=r"((r)[0]), "=r"((r)[1]), "=r"((r)[2]), "=r"((r)[3]) : "r"(addr))

#define MMA16816(c, a, b0, b1) \
    asm volatile("mma.sync.aligned.m16n8k16.row.col.f32.f16.f16.f32 " \
        "{%0,%1,%2,%3}, {%4,%5,%6,%7}, {%8,%9}, {%0,%1,%2,%3};" \
        : "+f"((c)[0]), "+f"((c)[1]), "+f"((c)[2]), "+f"((c)[3]) \
        : "r"((a)[0]), "r"((a)[1]), "r"((a)[2]), "r"((a)[3]), "r"(b0), "r"(b1))

// ---------------------------------------------------------------------------
// FP16 GEMM: C[M,N] = act(A[M,K] @ Bt[N,K]^T + bias)
//   CTA 128x128, BK=64 halves, 8 warps (2x4), warp tile 64x32.
//   3-stage cp.async pipeline, XOR-swizzled smem, ldmatrix + mma.m16n8k16.
//   OUTMODE: 0 = f32 only, 1 = f16 only, 2 = f32 (Cout) + f16 (Ch2)
// ---------------------------------------------------------------------------
#define STAGE_B 32768   // 16KB A + 16KB B
#define NST     3
#define GSMEM   (NST * STAGE_B)

template<int ACT, int OUTMODE>
__global__ void __launch_bounds__(256, 2)
gemm_f16(const __half* __restrict__ A, const __half* __restrict__ Bt,
         const float* __restrict__ bias, void* __restrict__ Cout,
         __half* __restrict__ Ch2, int M, int N, int K)
{
    extern __shared__ char smem[];
    const uint32_t sb = smem_u32(smem);
    const int tid  = threadIdx.x;
    const int lane = tid & 31;
    const int wid  = tid >> 5;
    const int wm   = wid >> 2;            // 0..1 (64-row slabs)
    const int wn   = wid & 3;             // 0..3 (32-col slabs)
    const int m0 = blockIdx.y * 128;
    const int n0 = blockIdx.x * 128;
    const int KT = K >> 6;                // k-tiles of 64 halves

    int lrowv[4]; uint32_t lsoffv[4]; int luv[4];
    #pragma unroll
    for (int i = 0; i < 4; i++) {
        int idx = i * 256 + tid;
        int row = idx >> 3, u = idx & 7;
        lrowv[i] = row; luv[i] = u;
        lsoffv[i] = (uint32_t)(row * 128 + ((u ^ (row & 7)) * 16));
    }

    auto load_stage = [&](int kt, int s) {
        const uint32_t sA = sb + s * STAGE_B;
        const uint32_t sB = sA + 16384;
        const int k0 = kt * 64;
        #pragma unroll
        for (int i = 0; i < 4; i++) {
            cp_async16(sA + lsoffv[i], A  + (size_t)(m0 + lrowv[i]) * K + k0 + luv[i] * 8);
            cp_async16(sB + lsoffv[i], Bt + (size_t)(n0 + lrowv[i]) * K + k0 + luv[i] * 8);
        }
    };

    const int seg  = lane >> 3;
    const int lrow = lane & 7;
    const int arow = wm * 64 + lrow + (seg & 1) * 8;
    const int auseg = seg >> 1;
    const int ax7  = arow & 7;
    const int brow = wn * 32 + lrow + (seg >> 1) * 8;
    const int buseg = seg & 1;
    const int bx7  = brow & 7;

    float acc[4][4][4];
    #pragma unroll
    for (int i = 0; i < 4; i++)
        #pragma unroll
        for (int j = 0; j < 4; j++)
            #pragma unroll
            for (int r = 0; r < 4; r++) acc[i][j][r] = 0.0f;

    load_stage(0, 0); CP_COMMIT();
    load_stage(1, 1); CP_COMMIT();

    for (int kt = 0; kt < KT; kt++) {
        CP_WAIT1();
        __syncthreads();
        if (kt + 2 < KT) load_stage(kt + 2, (kt + 2) % 3);
        CP_COMMIT();

        const uint32_t sA = sb + (kt % 3) * STAGE_B;
        const uint32_t sB = sA + 16384;
        #pragma unroll
        for (int kk = 0; kk < 4; kk++) {
            uint32_t af[4][4];
            #pragma unroll
            for (int am = 0; am < 4; am++) {
                uint32_t row = arow + am * 16;
                uint32_t unit = (uint32_t)((2 * kk + auseg) ^ ax7);
                LDSM4(af[am], sA + row * 128 + unit * 16);
            }
            uint32_t bf[2][4];
            #pragma unroll
            for (int bp = 0; bp < 2; bp++) {
                uint32_t row = brow + bp * 16;
                uint32_t unit = (uint32_t)((2 * kk + buseg) ^ bx7);
                LDSM4(bf[bp], sB + row * 128 + unit * 16);
            }
            #pragma unroll
            for (int am = 0; am < 4; am++)
                #pragma unroll
                for (int bn = 0; bn < 4; bn++)
                    MMA16816(acc[am][bn], af[am],
                             bf[bn >> 1][(bn & 1) * 2], bf[bn >> 1][(bn & 1) * 2 + 1]);
        }
    }

    // epilogue
    const int g   = lane >> 2;
    const int tig = lane & 3;
    #pragma unroll
    for (int am = 0; am < 4; am++) {
        #pragma unroll
        for (int bn = 0; bn < 4; bn++) {
            int grow = m0 + wm * 64 + am * 16 + g;
            int gcol = n0 + wn * 32 + bn * 8 + 2 * tig;
            float2 bb = *(const float2*)(bias + gcol);
            float v0 = acc[am][bn][0] + bb.x;
            float v1 = acc[am][bn][1] + bb.y;
            float v2 = acc[am][bn][2] + bb.x;
            float v3 = acc[am][bn][3] + bb.y;
            if (ACT) { v0 = gelu_f(v0); v1 = gelu_f(v1); v2 = gelu_f(v2); v3 = gelu_f(v3); }
            if (OUTMODE == 0 || OUTMODE == 2) {
                float* Cf = (float*)Cout;
                *(float2*)(Cf + (size_t)grow * N + gcol)       = make_float2(v0, v1);
                *(float2*)(Cf + (size_t)(grow + 8) * N + gcol) = make_float2(v2, v3);
            }
            if (OUTMODE == 1) {
                __half* Ch = (__half*)Cout;
                *(__half2*)(Ch + (size_t)grow * N + gcol)       = __floats2half2_rn(v0, v1);
                *(__half2*)(Ch + (size_t)(grow + 8) * N + gcol) = __floats2half2_rn(v2, v3);
            }
            if (OUTMODE == 2) {
                *(__half2*)(Ch2 + (size_t)grow * N + gcol)       = __floats2half2_rn(v0, v1);
                *(__half2*)(Ch2 + (size_t)(grow + 8) * N + gcol) = __floats2half2_rn(v2, v3);
            }
        }
    }
}

// ---------------------------------------------------------------------------
// Pre-pass: x -> fp16 ; transpose weights [K][N] f32 -> [N][K] fp16
// ---------------------------------------------------------------------------
__global__ void f2h_kernel(const float* __restrict__ in, __half* __restrict__ out, int n4) {
    int i = blockIdx.x * blockDim.x + threadIdx.x;
    if (i < n4) {
        float4 v = ((const float4*)in)[i];
        ((__half2*)out)[2 * i]     = __floats2half2_rn(v.x, v.y);
        ((__half2*)out)[2 * i + 1] = __floats2half2_rn(v.z, v.w);
    }
}

__global__ void transpose_f2h(const float* __restrict__ in, __half* __restrict__ out,
                              int R, int C) {   // in [R][C] -> out [C][R]
    __shared__ float t[32][33];
    int bx = blockIdx.x * 32;
    int by = blockIdx.y * 32;
    int tx = threadIdx.x, ty = threadIdx.y;
    #pragma unroll
    for (int i = 0; i < 32; i += 8)
        t[ty + i][tx] = in[(size_t)(by + ty + i) * C + bx + tx];
    __syncthreads();
    #pragma unroll
    for (int i = 0; i < 32; i += 8)
        out[(size_t)(bx + ty + i) * R + by + tx] = __float2half_rn(t[tx][ty + i]);
}

// ---------------------------------------------------------------------------
// Flash attention v2 (causal), Dh=64, register-resident.
// CTA = (batch-head, 128 q rows), 256 threads (8 warps, 16 rows each).
// K/V fp16 from scratch, cp.async double-buffered per 64-row kv block.
// S in mma accum registers -> softmax in registers -> P repacked in-register
// -> O accumulated in registers.
// smem: Q tile 16KB + 2 stages x (K 8KB + V 8KB) = 48KB.
// ---------------------------------------------------------------------------
#define AT_SMEM 49152

__global__ void __launch_bounds__(256, 2) flash_attn2(
    const __half* __restrict__ Qh, const __half* __restrict__ Kh,
    const __half* __restrict__ Vh, float* __restrict__ O)
{
    extern __shared__ char sma[];
    const uint32_t sb = smem_u32(sma);
    const uint32_t sQ = sb;
    const int tid = threadIdx.x;
    const int lane = tid & 31;
    const int w = tid >> 5;
    const int qt = (int)(gridDim.x - 1 - blockIdx.x);  // heavy CTAs first
    const int bh = blockIdx.y;
    const int b = bh >> 3, h = bh & 7;
    const int jend = 2 * qt + 2;

    const size_t hb = (size_t)b * SEQ * EMB + (size_t)h * DH;
    const __half* Qg = Qh + hb + (size_t)qt * 128 * EMB;
    const __half* Kg = Kh + hb;
    const __half* Vg = Vh + hb;

    auto load_q = [&]() {
        #pragma unroll
        for (int i = 0; i < 4; i++) {
            int idx = i * 256 + tid;
            int row = idx >> 3, u = idx & 7;
            uint32_t off = (uint32_t)(row * 128 + ((u ^ (row & 7)) * 16));
            cp_async16(sQ + off, Qg + (size_t)row * EMB + u * 8);
        }
    };
    auto load_kv = [&](int j, int s) {
        const uint32_t st = sb + 16384 + s * 16384;
        #pragma unroll
        for (int i = 0; i < 4; i++) {
            int idx = i * 256 + tid;
            if (idx < 512) {
                int row = idx >> 3, u = idx & 7;
                uint32_t off = (uint32_t)(row * 128 + ((u ^ (row & 7)) * 16));
                cp_async16(st + off, Kg + (size_t)(j * 64 + row) * EMB + u * 8);
            } else {
                int k2 = idx - 512;
                int row = k2 >> 3, u = k2 & 7;
                uint32_t off = (uint32_t)(row * 128 + ((u ^ (row & 7)) * 16));
                cp_async16(st + 8192 + off, Vg + (size_t)(j * 64 + row) * EMB + u * 8);
            }
        }
    };

    load_q(); load_kv(0, 0); CP_COMMIT();
    if (1 < jend) load_kv(1, 1);
    CP_COMMIT();
    CP_WAIT1();          // Q + kv0 landed
    __syncthreads();

    const int seg  = lane >> 3;
    const int lrow = lane & 7;
    const int g    = lane >> 2;
    const int tig  = lane & 3;

    // Q a-frags (persistent)
    uint32_t af[4][4];
    {
        int row = w * 16 + lrow + (seg & 1) * 8;
        #pragma unroll
        for (int kk = 0; kk < 4; kk++) {
            uint32_t u = (uint32_t)((2 * kk + (seg >> 1)) ^ (row & 7));
            LDSM4(af[kk], sQ + row * 128 + u * 16);
        }
    }

    float oacc[8][4];
    #pragma unroll
    for (int nf = 0; nf < 8; nf++)
        #pragma unroll
        for (int i = 0; i < 4; i++) oacc[nf][i] = 0.0f;

    float mA = -INFINITY, mB = -INFINITY, lA = 0.0f, lB = 0.0f;
    const int rowA = qt * 128 + w * 16 + g;   // global q row (rowB = rowA+8)

    for (int j = 0; j < jend; j++) {
        if (j > 0) { CP_WAIT1(); __syncthreads(); }
        const uint32_t sK = sb + 16384 + (j & 1) * 16384;
        const uint32_t sV = sK + 8192;

        // S = Q @ K^T  (8 n-frags of 8 cols)
        float sacc[8][4];
        #pragma unroll
        for (int nf = 0; nf < 8; nf++)
            #pragma unroll
            for (int i = 0; i < 4; i++) sacc[nf][i] = 0.0f;

        #pragma unroll
        for (int kk = 0; kk < 4; kk++) {
            #pragma unroll
            for (int ng = 0; ng < 4; ng++) {
                uint32_t kf[4];
                int row = ng * 16 + lrow + (seg >> 1) * 8;
                uint32_t u = (uint32_t)((2 * kk + (seg & 1)) ^ (row & 7));
                LDSM4(kf, sK + row * 128 + u * 16);
                MMA16816(sacc[2 * ng],     af[kk], kf[0], kf[1]);
                MMA16816(sacc[2 * ng + 1], af[kk], kf[2], kf[3]);
            }
        }

        // scale + causal mask
        const bool msk = (j >= 2 * qt);
        #pragma unroll
        for (int nf = 0; nf < 8; nf++) {
            #pragma unroll
            for (int i = 0; i < 4; i++) {
                float s = sacc[nf][i] * 0.125f;
                if (msk) {
                    int col = j * 64 + nf * 8 + 2 * tig + (i & 1);
                    int row = rowA + ((i >= 2) ? 8 : 0);
                    if (col > row) s = -INFINITY;
                }
                sacc[nf][i] = s;
            }
        }

        // online softmax (registers + quad shuffles)
        float mxA = -INFINITY, mxB = -INFINITY;
        #pragma unroll
        for (int nf = 0; nf < 8; nf++) {
            mxA = fmaxf(mxA, fmaxf(sacc[nf][0], sacc[nf][1]));
            mxB = fmaxf(mxB, fmaxf(sacc[nf][2], sacc[nf][3]));
        }
        mxA = fmaxf(mxA, __shfl_xor_sync(0xffffffffu, mxA, 1));
        mxA = fmaxf(mxA, __shfl_xor_sync(0xffffffffu, mxA, 2));
        mxB = fmaxf(mxB, __shfl_xor_sync(0xffffffffu, mxB, 1));
        mxB = fmaxf(mxB, __shfl_xor_sync(0xffffffffu, mxB, 2));

        float mnA = fmaxf(mA, mxA), mnB = fmaxf(mB, mxB);
        float cA = __expf(mA - mnA), cB = __expf(mB - mnB);
        mA = mnA; mB = mnB;

        float sA = 0.0f, sB = 0.0f;
        uint32_t pa[4][4];
        #pragma unroll
        for (int nf = 0; nf < 8; nf++) {
            float e0 = __expf(sacc[nf][0] - mnA);
            float e1 = __expf(sacc[nf][1] - mnA);
            float e2 = __expf(sacc[nf][2] - mnB);
            float e3 = __expf(sacc[nf][3] - mnB);
            sA += e0 + e1;
            sB += e2 + e3;
            __half2 lo = __floats2half2_rn(e0, e1);
            __half2 hi = __floats2half2_rn(e2, e3);
            int kk2 = nf >> 1, p = nf & 1;
            pa[kk2][p * 2]     = *(uint32_t*)&lo;   // row g   half of this k8
            pa[kk2][p * 2 + 1] = *(uint32_t*)&hi;   // row g+8 half of this k8
        }
        sA += __shfl_xor_sync(0xffffffffu, sA, 1);
        sA += __shfl_xor_sync(0xffffffffu, sA, 2);
        sB += __shfl_xor_sync(0xffffffffu, sB, 1);
        sB += __shfl_xor_sync(0xffffffffu, sB, 2);
        lA = lA * cA + sA;
        lB = lB * cB + sB;

        // rescale O
        #pragma unroll
        for (int nf = 0; nf < 8; nf++) {
            oacc[nf][0] *= cA; oacc[nf][1] *= cA;
            oacc[nf][2] *= cB; oacc[nf][3] *= cB;
        }

        // O += P @ V  (V b-frags via ldmatrix.trans on [kseq][dh] tile)
        #pragma unroll
        for (int kk2 = 0; kk2 < 4; kk2++) {
            #pragma unroll
            for (int ng = 0; ng < 4; ng++) {
                uint32_t vf[4];
                int row = kk2 * 16 + lrow + (seg & 1) * 8;
                uint32_t u = (uint32_t)((2 * ng + (seg >> 1)) ^ (row & 7));
                LDSM4T(vf, sV + row * 128 + u * 16);
                MMA16816(oacc[2 * ng],     pa[kk2], vf[0], vf[1]);
                MMA16816(oacc[2 * ng + 1], pa[kk2], vf[2], vf[3]);
            }
        }

        __syncthreads();
        if (j + 2 < jend) load_kv(j + 2, j & 1);
        CP_COMMIT();
    }

    // finalize: O / l -> global f32
    const float iA = 1.0f / lA;
    const float iB = 1.0f / lB;
    float* Ob = O + hb + (size_t)(qt * 128 + w * 16 + g) * EMB;
    #pragma unroll
    for (int nf = 0; nf < 8; nf++) {
        int col = nf * 8 + 2 * tig;
        *(float2*)(Ob + col)           = make_float2(oacc[nf][0] * iA, oacc[nf][1] * iA);
        *(float2*)(Ob + 8 * EMB + col) = make_float2(oacc[nf][2] * iB, oacc[nf][3] * iB);
    }
}

// ---------------------------------------------------------------------------
// Host launcher. Output layout: concat(k, v, out), each [2,2048,512] fp32.
// ---------------------------------------------------------------------------
extern "C" void kernel_launch(void* const* d_in, const int* in_sizes, int n_in,
                              void* d_out, int out_size)
{
    const float* x   = (const float*)d_in[0];
    const float* qW1 = (const float*)d_in[1];
    const float* qb1 = (const float*)d_in[2];
    const float* qW2 = (const float*)d_in[3];
    const float* qb2 = (const float*)d_in[4];
    const float* kW1 = (const float*)d_in[5];
    const float* kb1 = (const float*)d_in[6];
    const float* kW2 = (const float*)d_in[7];
    const float* kb2 = (const float*)d_in[8];
    const float* vW1 = (const float*)d_in[9];
    const float* vb1 = (const float*)d_in[10];
    const float* vW2 = (const float*)d_in[11];
    const float* vb2 = (const float*)d_in[12];

    float* outp = (float*)d_out;
    float* kOut = outp;
    float* vOut = outp + (size_t)MTOT * EMB;
    float* oOut = outp + (size_t)2 * MTOT * EMB;

    __half *Hh = nullptr, *Qh = nullptr, *Kh = nullptr, *Vh = nullptr, *xh = nullptr, *Wt = nullptr;
    cudaGetSymbolAddress((void**)&Hh, g_Hh);
    cudaGetSymbolAddress((void**)&Qh, g_Qh);
    cudaGetSymbolAddress((void**)&Kh, g_Kh);
    cudaGetSymbolAddress((void**)&Vh, g_Vh);
    cudaGetSymbolAddress((void**)&xh, g_xh);
    cudaGetSymbolAddress((void**)&Wt, g_Wt);

    const size_t WSZ = (size_t)EMB * HID;
    __half* qW1t = Wt + 0 * WSZ;
    __half* qW2t = Wt + 1 * WSZ;
    __half* kW1t = Wt + 2 * WSZ;
    __half* kW2t = Wt + 3 * WSZ;
    __half* vW1t = Wt + 4 * WSZ;
    __half* vW2t = Wt + 5 * WSZ;

    // Pre-pass
    f2h_kernel<<<(MTOT * EMB / 4 + 255) / 256, 256>>>(x, xh, MTOT * EMB / 4);
    dim3 tpb(32, 8);
    dim3 tg1(HID / 32, EMB / 32);   // W1 [512][2048] -> [2048][512]
    dim3 tg2(EMB / 32, HID / 32);   // W2 [2048][512] -> [512][2048]
    transpose_f2h<<<tg1, tpb>>>(qW1, qW1t, EMB, HID);
    transpose_f2h<<<tg2, tpb>>>(qW2, qW2t, HID, EMB);
    transpose_f2h<<<tg1, tpb>>>(kW1, kW1t, EMB, HID);
    transpose_f2h<<<tg2, tpb>>>(kW2, kW2t, HID, EMB);
    transpose_f2h<<<tg1, tpb>>>(vW1, vW1t, EMB, HID);
    transpose_f2h<<<tg2, tpb>>>(vW2, vW2t, HID, EMB);

    cudaFuncSetAttribute(gemm_f16<1,1>, cudaFuncAttributeMaxDynamicSharedMemorySize, GSMEM);
    cudaFuncSetAttribute(gemm_f16<0,1>, cudaFuncAttributeMaxDynamicSharedMemorySize, GSMEM);
    cudaFuncSetAttribute(gemm_f16<0,2>, cudaFuncAttributeMaxDynamicSharedMemorySize, GSMEM);
    cudaFuncSetAttribute(gemm_f16<1,2>, cudaFuncAttributeMaxDynamicSharedMemorySize, GSMEM);

    dim3 grid1(HID / 128, MTOT / 128);   // 16 x 32
    dim3 grid2(EMB / 128, MTOT / 128);   // 4  x 32

    // K path: f32 to d_out + f16 copy for attention
    gemm_f16<1,1><<<grid1, 256, GSMEM>>>(xh, kW1t, kb1, Hh, nullptr, MTOT, HID, EMB);
    gemm_f16<0,2><<<grid2, 256, GSMEM>>>(Hh, kW2t, kb2, kOut, Kh, MTOT, EMB, HID);
    // V path (trailing GELU): f32 + f16 copy
    gemm_f16<1,1><<<grid1, 256, GSMEM>>>(xh, vW1t, vb1, Hh, nullptr, MTOT, HID, EMB);
    gemm_f16<1,2><<<grid2, 256, GSMEM>>>(Hh, vW2t, vb2, vOut, Vh, MTOT, EMB, HID);
    // Q path: f16 only
    gemm_f16<1,1><<<grid1, 256, GSMEM>>>(xh, qW1t, qb1, Hh, nullptr, MTOT, HID, EMB);
    gemm_f16<0,1><<<grid2, 256, GSMEM>>>(Hh, qW2t, qb2, Qh, nullptr, MTOT, EMB, HID);

    // Attention (register-resident FA2)
    cudaFuncSetAttribute(flash_attn2, cudaFuncAttributeMaxDynamicSharedMemorySize, AT_SMEM);
    flash_attn2<<<dim3(SEQ / 128, NBATCH * NHEAD), 256, AT_SMEM>>>(Qh, Kh, Vh, oOut);
}